// round 7
// baseline (speedup 1.0000x reference)
#include <cuda_runtime.h>

#define NODES 336
#define NPC   8192
#define NUMCASE 2048
#define MIU_F 1.9e-05f
#define ALPHA_F 0.10471975511965977f   // 6*pi/180
#define QCOEF_F 73830.75f              // 0.5*1.225*ACOUSTIC^2
#define FULL 0xffffffffu

// 2 cases per 256-thread CTA: grid = 1024 -> single wave (6.9 CTAs/SM) AND
// ~55 resident warps/SM. Thread t handles node t (and t+256 if t<80) per case.
__global__ __launch_bounds__(256, 7) void dyn_kernel(
    const float* __restrict__ coords,
    const float* __restrict__ fields,
    const float* __restrict__ design,
    float2* __restrict__ out)
{
    const int c0 = blockIdx.x * 2;
    const int t = threadIdx.x;

    __shared__ float2 s_n0[2][NODES];
    __shared__ float2 s_f1[2][NODES];   // (u, v)
    __shared__ float  s_dl[2][NODES];   // delta
    __shared__ float  s_red[8][8];

    float2 n0[2][2];
    float pt[2][2];
    float d3[2] = {0.f, 0.f}, d4[2] = {0.f, 0.f};

    const float2* cf2 = (const float2*)coords;
    const float4* ff4 = (const float4*)fields;

    // ---- Phase 0: front-batched loads for both cases, stage stencil in smem ----
    #pragma unroll
    for (int cc = 0; cc < 2; cc++) {
        const int base = (c0 + cc) * NPC;
        #pragma unroll
        for (int k = 0; k < 2; k++) {
            int j = t + k * 256;
            bool valid = (k == 0) || (t < NODES - 256);
            if (valid) {
                float2 a = cf2[base + j];
                float2 b = cf2[base + NODES + j];
                float4 f1 = ff4[base + NODES + j];
                n0[cc][k] = a;
                pt[cc][k] = fields[4 * (base + j)];       // f0[:, :, 0]
                d3[cc] += design[5 * (base + j) + 3];
                d4[cc] += design[5 * (base + j) + 4];
                s_n0[cc][j] = a;
                s_f1[cc][j] = make_float2(f1.z, f1.w);
                float dx = b.x - a.x, dy = b.y - a.y;
                s_dl[cc][j] = sqrtf(dx * dx + dy * dy);
            }
        }
    }
    __syncthreads();

    // ---- Phase 1: recompute tau[j], tau[j+1] locally; accumulate forces ----
    float Fx[2] = {0.f, 0.f}, Fy[2] = {0.f, 0.f};
    #pragma unroll
    for (int cc = 0; cc < 2; cc++) {
        #pragma unroll
        for (int k = 0; k < 2; k++) {
            int j = t + k * 256;
            bool valid = (k == 0) || (t < NODES - 256);
            if (valid) {
                int jp  = (j + 1 == NODES) ? 0 : j + 1;
                int jpp = (jp + 1 == NODES) ? 0 : jp + 1;
                float2 a  = n0[cc][k];
                float2 b  = s_n0[cc][jp];
                float2 cn = s_n0[cc][jpp];
                float tx = b.x - a.x, ty = b.y - a.y;
                float tn = sqrtf(tx * tx + ty * ty);
                float2 f = s_f1[cc][j];
                float tau0 = MIU_F * ((f.x * tx + f.y * ty) / tn) / s_dl[cc][j];
                float tx1 = cn.x - b.x, ty1 = cn.y - b.y;
                float tn1 = sqrtf(tx1 * tx1 + ty1 * ty1);
                float2 fn = s_f1[cc][jp];
                float tau1 = MIU_F * ((fn.x * tx1 + fn.y * ty1) / tn1) / s_dl[cc][jp];
                float ta = 0.5f * (tau0 + tau1);
                // -Px = -pt*T.y ; -Py = +pt*T.x ; +50*tau_ave*T
                Fx[cc] += -pt[cc][k] * ty + 50.f * ta * tx;
                Fy[cc] +=  pt[cc][k] * tx + 50.f * ta * ty;
            }
        }
    }

    // ---- Block reduction of 8 values over 8 warps ----
    #pragma unroll
    for (int off = 16; off; off >>= 1) {
        #pragma unroll
        for (int cc = 0; cc < 2; cc++) {
            Fx[cc] += __shfl_down_sync(FULL, Fx[cc], off);
            Fy[cc] += __shfl_down_sync(FULL, Fy[cc], off);
            d3[cc] += __shfl_down_sync(FULL, d3[cc], off);
            d4[cc] += __shfl_down_sync(FULL, d4[cc], off);
        }
    }
    int warp = t >> 5, lane = t & 31;
    if (lane == 0) {
        #pragma unroll
        for (int cc = 0; cc < 2; cc++) {
            s_red[warp][4 * cc + 0] = Fx[cc];
            s_red[warp][4 * cc + 1] = Fy[cc];
            s_red[warp][4 * cc + 2] = d3[cc];
            s_red[warp][4 * cc + 3] = d4[cc];
        }
    }
    __syncthreads();

    // ---- Epilogue: threads 0 and 1 each finalize one case ----
    if (t < 2) {
        float fx = 0.f, fy = 0.f, s3 = 0.f, s4 = 0.f;
        #pragma unroll
        for (int w = 0; w < 8; w++) {
            fx += s_red[w][4 * t + 0];
            fy += s_red[w][4 * t + 1];
            s3 += s_red[w][4 * t + 2];
            s4 += s_red[w][4 * t + 3];
        }
        float Ma = s3 * (0.3f / (float)NODES) + 0.3f;
        float af = s4 * (ALPHA_F / (float)NODES);
        float ca = cosf(af), sa = sinf(af);
        float Fxn = fx * ca + fy * sa;
        float Fyn = fy * ca - Fxn * sa;   // reference uses Fx_new here (literal)
        float q = QCOEF_F * Ma * Ma;
        out[c0 + t] = make_float2(Fxn / q, Fyn / q);
    }
}

extern "C" void kernel_launch(void* const* d_in, const int* in_sizes, int n_in,
                              void* d_out, int out_size) {
    // metadata order: batch(int32), coords(f32), fields(f32), design(f32), num_case, nodes_num
    const float* coords = (const float*)d_in[1];
    const float* fields = (const float*)d_in[2];
    const float* design = (const float*)d_in[3];
    float2* out = (float2*)d_out;
    dyn_kernel<<<NUMCASE / 2, 256>>>(coords, fields, design, out);
}

// round 8
// speedup vs baseline: 1.1895x; 1.1895x over previous
#include <cuda_runtime.h>
#include <cstdint>

#define NODES 336
#define NPC   8192
#define NUMCASE 2048
#define MIU_F 1.9e-05f
#define ALPHA_F 0.10471975511965977f   // 6*pi/180
#define QCOEF_F 73830.75f              // 0.5*1.225*ACOUSTIC^2
#define FULL 0xffffffffu

#define CRD_BYTES (2 * NODES * 2 * 4)   // 5376
#define FLD_BYTES (2 * NODES * 4 * 4)   // 10752
#define DSG_BYTES (NODES * 5 * 4)       // 6720
#define TOT_BYTES (CRD_BYTES + FLD_BYTES + DSG_BYTES)  // 22848

__device__ __forceinline__ uint32_t smem_u32(const void* p) {
    return (uint32_t)__cvta_generic_to_shared(p);
}

__global__ __launch_bounds__(128) void dyn_kernel(
    const float* __restrict__ coords,
    const float* __restrict__ fields,
    const float* __restrict__ design,
    float2* __restrict__ out)
{
    const int c = blockIdx.x;
    const int t = threadIdx.x;

    __shared__ alignas(16) float2 s_crd[2 * NODES];   // n0 rows then n1 rows
    __shared__ alignas(16) float4 s_fld[2 * NODES];   // f0 rows then f1 rows
    __shared__ alignas(16) float  s_dsg[NODES * 5];
    __shared__ alignas(8)  uint64_t mbar;
    __shared__ float s_red[4][4];

    // ---- init barrier, issue 3 bulk async copies from one thread ----
    if (t == 0) {
        asm volatile("mbarrier.init.shared.b64 [%0], 1;" ::
                     "r"(smem_u32(&mbar)) : "memory");
    }
    __syncthreads();
    if (t == 0) {
        uint32_t mb = smem_u32(&mbar);
        asm volatile("mbarrier.arrive.expect_tx.shared.b64 _, [%0], %1;" ::
                     "r"(mb), "r"((uint32_t)TOT_BYTES) : "memory");
        const char* g_crd = (const char*)(coords + (size_t)c * NPC * 2);
        const char* g_fld = (const char*)(fields + (size_t)c * NPC * 4);
        const char* g_dsg = (const char*)(design + (size_t)c * NPC * 5);
        asm volatile("cp.async.bulk.shared::cta.global.mbarrier::complete_tx::bytes [%0], [%1], %2, [%3];"
                     :: "r"(smem_u32(s_crd)), "l"(g_crd), "r"((uint32_t)CRD_BYTES), "r"(mb) : "memory");
        asm volatile("cp.async.bulk.shared::cta.global.mbarrier::complete_tx::bytes [%0], [%1], %2, [%3];"
                     :: "r"(smem_u32(s_fld)), "l"(g_fld), "r"((uint32_t)FLD_BYTES), "r"(mb) : "memory");
        asm volatile("cp.async.bulk.shared::cta.global.mbarrier::complete_tx::bytes [%0], [%1], %2, [%3];"
                     :: "r"(smem_u32(s_dsg)), "l"(g_dsg), "r"((uint32_t)DSG_BYTES), "r"(mb) : "memory");
    }
    // ---- all threads wait on the mbarrier (parity 0) ----
    {
        uint32_t mb = smem_u32(&mbar);
        uint32_t done;
        asm volatile(
            "{\n\t.reg .pred p;\n\t"
            "mbarrier.try_wait.parity.acquire.cta.shared::cta.b64 p, [%1], 0;\n\t"
            "selp.b32 %0, 1, 0, p;\n\t}"
            : "=r"(done) : "r"(mb) : "memory");
        while (!done) {
            asm volatile(
                "{\n\t.reg .pred p;\n\t"
                "mbarrier.try_wait.parity.acquire.cta.shared::cta.b64 p, [%1], 0, 0x989680;\n\t"
                "selp.b32 %0, 1, 0, p;\n\t}"
                : "=r"(done) : "r"(mb) : "memory");
        }
    }

    // ---- compute from shared: thread t handles nodes t, t+128, t+256(<336) ----
    float Fx = 0.f, Fy = 0.f, d3 = 0.f, d4 = 0.f;
    #pragma unroll
    for (int k = 0; k < 3; k++) {
        int j = t + k * 128;
        bool valid = (k < 2) || (t < NODES - 256);
        if (valid) {
            int jp  = (j + 1 == NODES) ? 0 : j + 1;
            int jpp = (jp + 1 == NODES) ? 0 : jp + 1;
            float2 a  = s_crd[j];
            float2 b  = s_crd[jp];
            float2 cn = s_crd[jpp];
            float4 f0  = s_fld[j];
            float4 f1  = s_fld[NODES + j];
            float4 f1p = s_fld[NODES + jp];
            float2 a1  = s_crd[NODES + j];
            float2 b1  = s_crd[NODES + jp];

            // tau at j
            float tx = b.x - a.x, ty = b.y - a.y;
            float tn = sqrtf(tx * tx + ty * ty);
            float dx = a1.x - a.x, dy = a1.y - a.y;
            float dl = sqrtf(dx * dx + dy * dy);
            float tau0 = MIU_F * ((f1.z * tx + f1.w * ty) / tn) / dl;
            // tau at j+1
            float tx1 = cn.x - b.x, ty1 = cn.y - b.y;
            float tn1 = sqrtf(tx1 * tx1 + ty1 * ty1);
            float dx1 = b1.x - b.x, dy1 = b1.y - b.y;
            float dl1 = sqrtf(dx1 * dx1 + dy1 * dy1);
            float tau1 = MIU_F * ((f1p.z * tx1 + f1p.w * ty1) / tn1) / dl1;

            float ta = 0.5f * (tau0 + tau1);
            float pt = f0.x;
            // -Px = -pt*T.y ; -Py = +pt*T.x ; +50*tau_ave*T
            Fx += -pt * ty + 50.f * ta * tx;
            Fy +=  pt * tx + 50.f * ta * ty;
            d3 += s_dsg[5 * j + 3];
            d4 += s_dsg[5 * j + 4];
        }
    }

    // ---- block reduction over 4 warps ----
    #pragma unroll
    for (int off = 16; off; off >>= 1) {
        Fx += __shfl_down_sync(FULL, Fx, off);
        Fy += __shfl_down_sync(FULL, Fy, off);
        d3 += __shfl_down_sync(FULL, d3, off);
        d4 += __shfl_down_sync(FULL, d4, off);
    }
    int warp = t >> 5, lane = t & 31;
    if (lane == 0) {
        s_red[warp][0] = Fx;
        s_red[warp][1] = Fy;
        s_red[warp][2] = d3;
        s_red[warp][3] = d4;
    }
    __syncthreads();

    if (t == 0) {
        float fx = 0.f, fy = 0.f, s3 = 0.f, s4 = 0.f;
        #pragma unroll
        for (int w = 0; w < 4; w++) {
            fx += s_red[w][0];
            fy += s_red[w][1];
            s3 += s_red[w][2];
            s4 += s_red[w][3];
        }
        float Ma = s3 * (0.3f / (float)NODES) + 0.3f;
        float af = s4 * (ALPHA_F / (float)NODES);
        float ca = cosf(af), sa = sinf(af);
        float Fxn = fx * ca + fy * sa;
        float Fyn = fy * ca - Fxn * sa;   // reference uses Fx_new here (literal)
        float q = QCOEF_F * Ma * Ma;
        out[c] = make_float2(Fxn / q, Fyn / q);
    }
}

extern "C" void kernel_launch(void* const* d_in, const int* in_sizes, int n_in,
                              void* d_out, int out_size) {
    // metadata order: batch(int32), coords(f32), fields(f32), design(f32), num_case, nodes_num
    const float* coords = (const float*)d_in[1];
    const float* fields = (const float*)d_in[2];
    const float* design = (const float*)d_in[3];
    float2* out = (float2*)d_out;
    dyn_kernel<<<NUMCASE, 128>>>(coords, fields, design, out);
}